// round 2
// baseline (speedup 1.0000x reference)
#include <cuda_runtime.h>
#include <cstdint>

// Problem dims
#define NV 64
#define NT 8192
#define NDA 256
#define NDS 256
#define NKR 8
#define NDU 64
#define NKA 40
#define M_TOTAL (NV * NT)  // 524288

// Output layout (float32, tuple flattened in reference-return order)
#define OFF_PDET 0
#define OFF_TAUX 1
#define OFF_YHAT 2
#define OFF_E    42
#define OFF_EV   (OFF_E + M_TOTAL)          // 524330
#define OFF_RV   (OFF_EV + NV)              // 524394
#define OFF_IV   (OFF_RV + NV)              // 524458
#define OFF_ST   (OFF_IV + NV)              // 524522
#define OFF_EN   (OFF_ST + M_TOTAL)         // 1048810
#define OFF_FLAG (OFF_EN + M_TOTAL)         // 1573098

// GEMM tiling
#define BM 128
#define BN 256
#define BK 16
#define PADM 130                 // As row stride (even -> 8B-aligned float2 rows)
#define NCHUNKS (NDA / BK)       // 16
#define GEMM_BLOCKS (M_TOTAL / BM)  // 4096

// -------- device scratch (no allocations allowed) --------
__device__ float  g_Wt[NDA * NDS];   // Wwin^T : Wt[d*256 + s] = Wwin[s*256 + d]
__device__ float  g_zsn[NDS];        // normalized zs
__device__ float  g_rview[NV];
__device__ double g_part[GEMM_BLOCKS];  // per-CTA sum of e (for E_view)

// -------- small PTX helpers --------
__device__ __forceinline__ unsigned long long dup2(float x) {
    unsigned long long r;
    unsigned u = __float_as_uint(x);
    asm("mov.b64 %0, {%1, %1};" : "=l"(r) : "r"(u));
    return r;
}
__device__ __forceinline__ void unpack2(unsigned long long v, float& lo, float& hi) {
    unsigned a, b;
    asm("mov.b64 {%0, %1}, %2;" : "=r"(a), "=r"(b) : "l"(v));
    lo = __uint_as_float(a);
    hi = __uint_as_float(b);
}
#define FMA2(d, a, b) asm("fma.rn.f32x2 %0, %1, %2, %0;" : "+l"(d) : "l"(a), "l"(b))

__device__ __forceinline__ void cp16(uint32_t saddr, const void* gaddr) {
    asm volatile("cp.async.cg.shared.global [%0], [%1], 16;" :: "r"(saddr), "l"(gaddr));
}
#define CP_COMMIT() asm volatile("cp.async.commit_group;")
#define CP_WAIT0()  asm volatile("cp.async.wait_group 0;" ::: "memory")

// ============================================================
// Kernel T: transpose Wwin (256x256) -> g_Wt
// ============================================================
__global__ void k_transpose(const float* __restrict__ W) {
    __shared__ float tile[32][33];
    int x = blockIdx.x * 32 + threadIdx.x;  // d
    int y = blockIdx.y * 32 + threadIdx.y;  // s
#pragma unroll
    for (int j = 0; j < 32; j += 8)
        tile[threadIdx.y + j][threadIdx.x] = W[(y + j) * NDA + x];
    __syncthreads();
    int xs = blockIdx.y * 32 + threadIdx.x;  // s
    int yd = blockIdx.x * 32 + threadIdx.y;  // d
#pragma unroll
    for (int j = 0; j < 32; j += 8)
        g_Wt[(yd + j) * NDS + xs] = tile[threadIdx.x][threadIdx.y + j];
}

// ============================================================
// Kernel A: scalars — zs, s, tau_x, p_det, y_hat, r_view, zsn
// ============================================================
__global__ void k_scalars(const float* __restrict__ alpha, const float* __restrict__ pi,
                          const float* __restrict__ US,
                          const float* __restrict__ Ws_w, const float* __restrict__ Ws_b,
                          const float* __restrict__ det_w, const float* __restrict__ det_b,
                          const float* __restrict__ cls_w, const float* __restrict__ cls_b,
                          const float* __restrict__ tau_c0, const float* __restrict__ lamU,
                          const float* __restrict__ lamC, const float* __restrict__ lamP,
                          const float* __restrict__ lamPi, const float* __restrict__ nu,
                          const float* __restrict__ risk, float* __restrict__ out) {
    __shared__ float us[NKR * NDU];   // 512
    __shared__ float zs[NDS];
    __shared__ float red[256];
    int t = threadIdx.x;  // 256 threads
    us[t] = US[t];
    us[t + 256] = US[t + 256];
    __syncthreads();

    float z = Ws_b[t];
#pragma unroll 4
    for (int k = 0; k < NKR * NDU; k++) z += Ws_w[t * (NKR * NDU) + k] * us[k];
    zs[t] = z;
    __syncthreads();

    // reduce sum of squares
    red[t] = z * z;
    __syncthreads();
    for (int s = 128; s > 0; s >>= 1) { if (t < s) red[t] += red[t + s]; __syncthreads(); }
    float ss = red[0];
    __syncthreads();

    // reduce detection score
    red[t] = z * det_w[t];
    __syncthreads();
    for (int s = 128; s > 0; s >>= 1) { if (t < s) red[t] += red[t + s]; __syncthreads(); }
    float sdet = red[0] + det_b[0];
    __syncthreads();

    float norm = fmaxf(sqrtf(ss), 1e-12f);
    g_zsn[t] = zs[t] / norm;

    if (t < NKA) {
        float y = cls_b[t];
#pragma unroll 4
        for (int j = 0; j < NDS; j++) y += cls_w[t * NDS + j] * zs[j];
        out[OFF_YHAT + t] = 1.0f / (1.0f + expf(-y));
    }
    if (t < NV) {
        float r = -0.5f * alpha[t];
        g_rview[t] = r;
        out[OFF_RV + t] = r;
    }
    if (t == 0) {
        float ha = 0.0f;
        for (int i = 0; i < NV; i++) { float a = alpha[i]; ha += a * logf(a + 1e-8f); }
        float Ca = 1.0f - (-ha) / logf((float)NV);
        float hp = 0.0f;
        for (int i = 0; i < NKR; i++) { float p = pi[i]; hp += p * logf(p + 1e-8f); }
        float up = (-hp) / logf((float)NKR);
        float tx = tau_c0[0] - lamU[0] * nu[0] - lamC[0] * Ca + lamP[0] * risk[0] + lamPi[0] * up;
        out[OFF_TAUX] = tx;
        out[OFF_PDET] = 1.0f / (1.0f + expf(-(sdet - tx)));
    }
}

// ============================================================
// Kernel B: fused fp32 GEMM (f32x2 FFMA) + row reduce -> e
//   C[m][s] = sum_d h[m][d] * Wt[d][s];  e[m] = (C·zsn) / max(||C||,1e-12)
// ============================================================
struct SmemB {
    float As[2][BK][PADM];  // 16.25 KB
    float Bs[2][BK][BN];    // 32 KB
    float zsn[NDS];         // 1 KB
    double wsum[8];
};

extern __shared__ char smem_raw[];

__global__ void __launch_bounds__(256, 1)
k_gemm(const float* __restrict__ A, float* __restrict__ out) {
    SmemB& S = *reinterpret_cast<SmemB*>(smem_raw);
    const int tid = threadIdx.x;
    const int w = tid >> 5;      // warp 0..7 -> rows w*16 .. w*16+15
    const int lane = tid & 31;   // cols lane*4..+3 and 128+lane*4..+3
    const int m0 = blockIdx.x * BM;

    S.zsn[tid] = g_zsn[tid];

    // A-loader mapping: thread handles (r0,q0) and (r1,q0): 4 k-floats each
    const int r0 = tid >> 2;         // 0..63
    const int q0 = tid & 3;          // k-quad
    const int r1 = r0 + 64;

    const uint32_t bs0 = (uint32_t)__cvta_generic_to_shared(&S.Bs[0][0][0]);
    const uint32_t bs1 = (uint32_t)__cvta_generic_to_shared(&S.Bs[1][0][0]);

    // ---- prologue: stage chunk 0 ----
    {
        const float* gb = g_Wt;  // chunk 0: contiguous 16KB
#pragma unroll
        for (int j = 0; j < 4; j++)
            cp16(bs0 + tid * 16 + j * 4096, gb + tid * 4 + j * 1024);
        CP_COMMIT();
        float4 pa0 = *reinterpret_cast<const float4*>(&A[(size_t)(m0 + r0) * NDA + q0 * 4]);
        float4 pa1 = *reinterpret_cast<const float4*>(&A[(size_t)(m0 + r1) * NDA + q0 * 4]);
        S.As[0][q0 * 4 + 0][r0] = pa0.x; S.As[0][q0 * 4 + 1][r0] = pa0.y;
        S.As[0][q0 * 4 + 2][r0] = pa0.z; S.As[0][q0 * 4 + 3][r0] = pa0.w;
        S.As[0][q0 * 4 + 0][r1] = pa1.x; S.As[0][q0 * 4 + 1][r1] = pa1.y;
        S.As[0][q0 * 4 + 2][r1] = pa1.z; S.As[0][q0 * 4 + 3][r1] = pa1.w;
        CP_WAIT0();
        __syncthreads();
    }

    unsigned long long acc[8][8];
#pragma unroll
    for (int p = 0; p < 8; p++)
#pragma unroll
        for (int c = 0; c < 8; c++) acc[p][c] = 0ull;

    for (int ki = 0; ki < NCHUNKS; ki++) {
        const int cur = ki & 1, nxt = cur ^ 1;
        const bool more = (ki + 1) < NCHUNKS;
        float4 pa0, pa1;
        if (more) {
            const float* gb = g_Wt + (size_t)(ki + 1) * BK * BN;
            const uint32_t bsn = (nxt ? bs1 : bs0);
#pragma unroll
            for (int j = 0; j < 4; j++)
                cp16(bsn + tid * 16 + j * 4096, gb + tid * 4 + j * 1024);
            CP_COMMIT();
            pa0 = *reinterpret_cast<const float4*>(&A[(size_t)(m0 + r0) * NDA + (ki + 1) * BK + q0 * 4]);
            pa1 = *reinterpret_cast<const float4*>(&A[(size_t)(m0 + r1) * NDA + (ki + 1) * BK + q0 * 4]);
        }
        // ---- compute chunk 'cur' ----
#pragma unroll
        for (int k = 0; k < BK; k++) {
            unsigned long long a2[8];
#pragma unroll
            for (int p = 0; p < 8; p++)
                a2[p] = *reinterpret_cast<const unsigned long long*>(&S.As[cur][k][w * 16 + 2 * p]);
            float4 b0 = *reinterpret_cast<const float4*>(&S.Bs[cur][k][lane * 4]);
            float4 b1 = *reinterpret_cast<const float4*>(&S.Bs[cur][k][128 + lane * 4]);
            unsigned long long bb[8];
            bb[0] = dup2(b0.x); bb[1] = dup2(b0.y); bb[2] = dup2(b0.z); bb[3] = dup2(b0.w);
            bb[4] = dup2(b1.x); bb[5] = dup2(b1.y); bb[6] = dup2(b1.z); bb[7] = dup2(b1.w);
#pragma unroll
            for (int p = 0; p < 8; p++) {
#pragma unroll
                for (int c = 0; c < 8; c++) FMA2(acc[p][c], a2[p], bb[c]);
            }
        }
        if (more) {
            S.As[nxt][q0 * 4 + 0][r0] = pa0.x; S.As[nxt][q0 * 4 + 1][r0] = pa0.y;
            S.As[nxt][q0 * 4 + 2][r0] = pa0.z; S.As[nxt][q0 * 4 + 3][r0] = pa0.w;
            S.As[nxt][q0 * 4 + 0][r1] = pa1.x; S.As[nxt][q0 * 4 + 1][r1] = pa1.y;
            S.As[nxt][q0 * 4 + 2][r1] = pa1.z; S.As[nxt][q0 * 4 + 3][r1] = pa1.w;
            CP_WAIT0();
            __syncthreads();
        }
    }

    // ---- epilogue: per-row sumsq & dot(zsn), warp butterfly reduce ----
    float ssq[16], dt[16];
#pragma unroll
    for (int p = 0; p < 8; p++) {
        float s0 = 0.f, s1 = 0.f, d0 = 0.f, d1 = 0.f;
#pragma unroll
        for (int c = 0; c < 8; c++) {
            int col = (c < 4) ? (lane * 4 + c) : (128 + lane * 4 + (c - 4));
            float zz = S.zsn[col];
            float lo, hi;
            unpack2(acc[p][c], lo, hi);
            s0 += lo * lo; d0 += lo * zz;
            s1 += hi * hi; d1 += hi * zz;
        }
        ssq[2 * p] = s0; dt[2 * p] = d0;
        ssq[2 * p + 1] = s1; dt[2 * p + 1] = d1;
    }
#pragma unroll
    for (int i = 0; i < 16; i++) {
#pragma unroll
        for (int off = 16; off > 0; off >>= 1) {
            ssq[i] += __shfl_xor_sync(0xFFFFFFFFu, ssq[i], off);
            dt[i]  += __shfl_xor_sync(0xFFFFFFFFu, dt[i],  off);
        }
    }
    if (lane == 0) {
        double wacc = 0.0;
#pragma unroll
        for (int i = 0; i < 16; i++) {
            float e = dt[i] / fmaxf(sqrtf(ssq[i]), 1e-12f);
            out[OFF_E + m0 + w * 16 + i] = e;
            wacc += (double)e;
        }
        S.wsum[w] = wacc;
    }
    __syncthreads();
    if (tid == 0) {
        double s = 0.0;
        for (int ww = 0; ww < 8; ww++) s += S.wsum[ww];
        g_part[blockIdx.x] = s;
    }
}

// ============================================================
// Kernel C: starts / ends from e
// ============================================================
__global__ void k_intervals(const float* __restrict__ out_ro, float* __restrict__ out) {
    int m = blockIdx.x * blockDim.x + threadIdx.x;
    if (m >= M_TOTAL) return;
    int v = m >> 13;          // /8192
    int t = m & (NT - 1);
    float r = g_rview[v];
    const float* e = out_ro + OFF_E;
    bool I  = e[m] >= r;
    bool Ip = (t > 0)      ? (e[m - 1] >= r) : false;
    bool In = (t < NT - 1) ? (e[m + 1] >= r) : false;
    out[OFF_ST + m] = (I && !Ip) ? 1.0f : 0.0f;
    out[OFF_EN + m] = (I && !In) ? 1.0f : 0.0f;
}

// ============================================================
// Kernel D: E_view, I_view, flag_unknown
// ============================================================
__global__ void k_final(float* __restrict__ out) {
    int t = threadIdx.x;  // 64 threads
    double s = 0.0;
    const int per_view = NT / BM;  // 64 CTAs per view
    for (int i = 0; i < per_view; i++) s += g_part[t * per_view + i];
    float ev = (float)(s / (double)NT);
    out[OFF_EV + t] = ev;
    bool iv = ev >= g_rview[t];
    out[OFF_IV + t] = iv ? 1.0f : 0.0f;
    int any = __syncthreads_or(iv ? 1 : 0);
    if (t == 0)
        out[OFF_FLAG] = ((out[OFF_PDET] >= 0.5f) && !any) ? 1.0f : 0.0f;
}

// ============================================================
extern "C" void kernel_launch(void* const* d_in, const int* in_sizes, int n_in,
                              void* d_out, int out_size) {
    const float* h      = (const float*)d_in[0];
    const float* alpha  = (const float*)d_in[1];
    const float* pi     = (const float*)d_in[2];
    const float* US     = (const float*)d_in[3];
    // d_in[4]=Wc_w, d_in[5]=Wc_b : unused downstream (zc dead)
    const float* Ws_w   = (const float*)d_in[6];
    const float* Ws_b   = (const float*)d_in[7];
    const float* det_w  = (const float*)d_in[8];
    const float* det_b  = (const float*)d_in[9];
    const float* cls_w  = (const float*)d_in[10];
    const float* cls_b  = (const float*)d_in[11];
    const float* Wwin   = (const float*)d_in[12];
    const float* tau_c0 = (const float*)d_in[13];
    const float* lamU   = (const float*)d_in[14];
    const float* lamC   = (const float*)d_in[15];
    const float* lamP   = (const float*)d_in[16];
    const float* lamPi  = (const float*)d_in[17];
    const float* nu     = (const float*)d_in[18];
    const float* risk   = (const float*)d_in[19];
    float* out = (float*)d_out;

    static bool attr_set = false;
    if (!attr_set) {
        cudaFuncSetAttribute(k_gemm, cudaFuncAttributeMaxDynamicSharedMemorySize,
                             (int)sizeof(SmemB));
        attr_set = true;
    }

    k_transpose<<<dim3(8, 8), dim3(32, 8)>>>(Wwin);
    k_scalars<<<1, 256>>>(alpha, pi, US, Ws_w, Ws_b, det_w, det_b, cls_w, cls_b,
                          tau_c0, lamU, lamC, lamP, lamPi, nu, risk, out);
    k_gemm<<<GEMM_BLOCKS, 256, sizeof(SmemB)>>>(h, out);
    k_intervals<<<(M_TOTAL + 255) / 256, 256>>>(out, out);
    k_final<<<1, NV>>>(out);
}

// round 7
// speedup vs baseline: 1.0007x; 1.0007x over previous
#include <cuda_runtime.h>
#include <cstdint>

// Problem dims
#define NV 64
#define NT 8192
#define NDA 256
#define NDS 256
#define NKR 8
#define NDU 64
#define NKA 40
#define M_TOTAL (NV * NT)  // 524288

// Output layout (float32, tuple flattened in reference-return order)
#define OFF_PDET 0
#define OFF_TAUX 1
#define OFF_YHAT 2
#define OFF_E    42
#define OFF_EV   (OFF_E + M_TOTAL)          // 524330
#define OFF_RV   (OFF_EV + NV)              // 524394
#define OFF_IV   (OFF_RV + NV)              // 524458
#define OFF_ST   (OFF_IV + NV)              // 524522
#define OFF_EN   (OFF_ST + M_TOTAL)         // 1048810
#define OFF_FLAG (OFF_EN + M_TOTAL)         // 1573098

// GEMM tiling
#define BM 128
#define BN 256
#define BK 16
#define PADM 130                 // As row stride (even -> 8B-aligned float2 rows)
#define NCHUNKS (NDA / BK)       // 16
#define GEMM_BLOCKS (M_TOTAL / BM)  // 4096

// -------- device scratch (no allocations allowed) --------
__device__ float  g_Wt[NDA * NDS];   // Wwin^T : Wt[d*256 + s] = Wwin[s*256 + d]
__device__ float  g_zsn[NDS];        // normalized zs
__device__ float  g_rview[NV];
__device__ double g_part[GEMM_BLOCKS];  // per-CTA sum of e (for E_view)

// -------- small PTX helpers --------
__device__ __forceinline__ unsigned long long dup2(float x) {
    unsigned long long r;
    unsigned u = __float_as_uint(x);
    asm("mov.b64 %0, {%1, %1};" : "=l"(r) : "r"(u));
    return r;
}
__device__ __forceinline__ void unpack2(unsigned long long v, float& lo, float& hi) {
    unsigned a, b;
    asm("mov.b64 {%0, %1}, %2;" : "=r"(a), "=r"(b) : "l"(v));
    lo = __uint_as_float(a);
    hi = __uint_as_float(b);
}
#define FMA2(d, a, b) asm("fma.rn.f32x2 %0, %1, %2, %0;" : "+l"(d) : "l"(a), "l"(b))

__device__ __forceinline__ void cp16(uint32_t saddr, const void* gaddr) {
    asm volatile("cp.async.cg.shared.global [%0], [%1], 16;" :: "r"(saddr), "l"(gaddr));
}
#define CP_COMMIT() asm volatile("cp.async.commit_group;")
#define CP_WAIT0()  asm volatile("cp.async.wait_group 0;" ::: "memory")

// ============================================================
// Kernel T: transpose Wwin (256x256) -> g_Wt
// ============================================================
__global__ void k_transpose(const float* __restrict__ W) {
    __shared__ float tile[32][33];
    int x = blockIdx.x * 32 + threadIdx.x;  // d
    int y = blockIdx.y * 32 + threadIdx.y;  // s
#pragma unroll
    for (int j = 0; j < 32; j += 8)
        tile[threadIdx.y + j][threadIdx.x] = W[(y + j) * NDA + x];
    __syncthreads();
    int xs = blockIdx.y * 32 + threadIdx.x;  // s
    int yd = blockIdx.x * 32 + threadIdx.y;  // d
#pragma unroll
    for (int j = 0; j < 32; j += 8)
        g_Wt[(yd + j) * NDS + xs] = tile[threadIdx.x][threadIdx.y + j];
}

// ============================================================
// Kernel A: scalars — zs, s, tau_x, p_det, y_hat, r_view, zsn
// ============================================================
__global__ void k_scalars(const float* __restrict__ alpha, const float* __restrict__ pi,
                          const float* __restrict__ US,
                          const float* __restrict__ Ws_w, const float* __restrict__ Ws_b,
                          const float* __restrict__ det_w, const float* __restrict__ det_b,
                          const float* __restrict__ cls_w, const float* __restrict__ cls_b,
                          const float* __restrict__ tau_c0, const float* __restrict__ lamU,
                          const float* __restrict__ lamC, const float* __restrict__ lamP,
                          const float* __restrict__ lamPi, const float* __restrict__ nu,
                          const float* __restrict__ risk, float* __restrict__ out) {
    __shared__ float us[NKR * NDU];   // 512
    __shared__ float zs[NDS];
    __shared__ float red[256];
    int t = threadIdx.x;  // 256 threads
    us[t] = US[t];
    us[t + 256] = US[t + 256];
    __syncthreads();

    float z = Ws_b[t];
#pragma unroll 4
    for (int k = 0; k < NKR * NDU; k++) z += Ws_w[t * (NKR * NDU) + k] * us[k];
    zs[t] = z;
    __syncthreads();

    // reduce sum of squares
    red[t] = z * z;
    __syncthreads();
    for (int s = 128; s > 0; s >>= 1) { if (t < s) red[t] += red[t + s]; __syncthreads(); }
    float ss = red[0];
    __syncthreads();

    // reduce detection score
    red[t] = z * det_w[t];
    __syncthreads();
    for (int s = 128; s > 0; s >>= 1) { if (t < s) red[t] += red[t + s]; __syncthreads(); }
    float sdet = red[0] + det_b[0];
    __syncthreads();

    float norm = fmaxf(sqrtf(ss), 1e-12f);
    g_zsn[t] = zs[t] / norm;

    if (t < NKA) {
        float y = cls_b[t];
#pragma unroll 4
        for (int j = 0; j < NDS; j++) y += cls_w[t * NDS + j] * zs[j];
        out[OFF_YHAT + t] = 1.0f / (1.0f + expf(-y));
    }
    if (t < NV) {
        float r = -0.5f * alpha[t];
        g_rview[t] = r;
        out[OFF_RV + t] = r;
    }
    if (t == 0) {
        float ha = 0.0f;
        for (int i = 0; i < NV; i++) { float a = alpha[i]; ha += a * logf(a + 1e-8f); }
        float Ca = 1.0f - (-ha) / logf((float)NV);
        float hp = 0.0f;
        for (int i = 0; i < NKR; i++) { float p = pi[i]; hp += p * logf(p + 1e-8f); }
        float up = (-hp) / logf((float)NKR);
        float tx = tau_c0[0] - lamU[0] * nu[0] - lamC[0] * Ca + lamP[0] * risk[0] + lamPi[0] * up;
        out[OFF_TAUX] = tx;
        out[OFF_PDET] = 1.0f / (1.0f + expf(-(sdet - tx)));
    }
}

// ============================================================
// Kernel B: fused fp32 GEMM (f32x2 FFMA) + row reduce -> e
//   C[m][s] = sum_d h[m][d] * Wt[d][s];  e[m] = (C·zsn) / max(||C||,1e-12)
// ============================================================
struct SmemB {
    float As[2][BK][PADM];  // 16.25 KB
    float Bs[2][BK][BN];    // 32 KB
    float zsn[NDS];         // 1 KB
    double wsum[8];
};

extern __shared__ char smem_raw[];

__global__ void __launch_bounds__(256, 1)
k_gemm(const float* __restrict__ A, float* __restrict__ out) {
    SmemB& S = *reinterpret_cast<SmemB*>(smem_raw);
    const int tid = threadIdx.x;
    const int w = tid >> 5;      // warp 0..7 -> rows w*16 .. w*16+15
    const int lane = tid & 31;   // cols lane*4..+3 and 128+lane*4..+3
    const int m0 = blockIdx.x * BM;

    S.zsn[tid] = g_zsn[tid];

    // A-loader mapping: thread handles (r0,q0) and (r1,q0): 4 k-floats each
    const int r0 = tid >> 2;         // 0..63
    const int q0 = tid & 3;          // k-quad
    const int r1 = r0 + 64;

    const uint32_t bs0 = (uint32_t)__cvta_generic_to_shared(&S.Bs[0][0][0]);
    const uint32_t bs1 = (uint32_t)__cvta_generic_to_shared(&S.Bs[1][0][0]);

    // ---- prologue: stage chunk 0 ----
    {
        const float* gb = g_Wt;  // chunk 0: contiguous 16KB
#pragma unroll
        for (int j = 0; j < 4; j++)
            cp16(bs0 + tid * 16 + j * 4096, gb + tid * 4 + j * 1024);
        CP_COMMIT();
        float4 pa0 = *reinterpret_cast<const float4*>(&A[(size_t)(m0 + r0) * NDA + q0 * 4]);
        float4 pa1 = *reinterpret_cast<const float4*>(&A[(size_t)(m0 + r1) * NDA + q0 * 4]);
        S.As[0][q0 * 4 + 0][r0] = pa0.x; S.As[0][q0 * 4 + 1][r0] = pa0.y;
        S.As[0][q0 * 4 + 2][r0] = pa0.z; S.As[0][q0 * 4 + 3][r0] = pa0.w;
        S.As[0][q0 * 4 + 0][r1] = pa1.x; S.As[0][q0 * 4 + 1][r1] = pa1.y;
        S.As[0][q0 * 4 + 2][r1] = pa1.z; S.As[0][q0 * 4 + 3][r1] = pa1.w;
        CP_WAIT0();
        __syncthreads();
    }

    unsigned long long acc[8][8];
#pragma unroll
    for (int p = 0; p < 8; p++)
#pragma unroll
        for (int c = 0; c < 8; c++) acc[p][c] = 0ull;

    for (int ki = 0; ki < NCHUNKS; ki++) {
        const int cur = ki & 1, nxt = cur ^ 1;
        const bool more = (ki + 1) < NCHUNKS;
        float4 pa0, pa1;
        if (more) {
            const float* gb = g_Wt + (size_t)(ki + 1) * BK * BN;
            const uint32_t bsn = (nxt ? bs1 : bs0);
#pragma unroll
            for (int j = 0; j < 4; j++)
                cp16(bsn + tid * 16 + j * 4096, gb + tid * 4 + j * 1024);
            CP_COMMIT();
            pa0 = *reinterpret_cast<const float4*>(&A[(size_t)(m0 + r0) * NDA + (ki + 1) * BK + q0 * 4]);
            pa1 = *reinterpret_cast<const float4*>(&A[(size_t)(m0 + r1) * NDA + (ki + 1) * BK + q0 * 4]);
        }
        // ---- compute chunk 'cur' ----
#pragma unroll
        for (int k = 0; k < BK; k++) {
            unsigned long long a2[8];
#pragma unroll
            for (int p = 0; p < 8; p++)
                a2[p] = *reinterpret_cast<const unsigned long long*>(&S.As[cur][k][w * 16 + 2 * p]);
            float4 b0 = *reinterpret_cast<const float4*>(&S.Bs[cur][k][lane * 4]);
            float4 b1 = *reinterpret_cast<const float4*>(&S.Bs[cur][k][128 + lane * 4]);
            unsigned long long bb[8];
            bb[0] = dup2(b0.x); bb[1] = dup2(b0.y); bb[2] = dup2(b0.z); bb[3] = dup2(b0.w);
            bb[4] = dup2(b1.x); bb[5] = dup2(b1.y); bb[6] = dup2(b1.z); bb[7] = dup2(b1.w);
#pragma unroll
            for (int p = 0; p < 8; p++) {
#pragma unroll
                for (int c = 0; c < 8; c++) FMA2(acc[p][c], a2[p], bb[c]);
            }
        }
        if (more) {
            S.As[nxt][q0 * 4 + 0][r0] = pa0.x; S.As[nxt][q0 * 4 + 1][r0] = pa0.y;
            S.As[nxt][q0 * 4 + 2][r0] = pa0.z; S.As[nxt][q0 * 4 + 3][r0] = pa0.w;
            S.As[nxt][q0 * 4 + 0][r1] = pa1.x; S.As[nxt][q0 * 4 + 1][r1] = pa1.y;
            S.As[nxt][q0 * 4 + 2][r1] = pa1.z; S.As[nxt][q0 * 4 + 3][r1] = pa1.w;
            CP_WAIT0();
            __syncthreads();
        }
    }

    // ---- epilogue: per-row sumsq & dot(zsn), warp butterfly reduce ----
    float ssq[16], dt[16];
#pragma unroll
    for (int p = 0; p < 8; p++) {
        float s0 = 0.f, s1 = 0.f, d0 = 0.f, d1 = 0.f;
#pragma unroll
        for (int c = 0; c < 8; c++) {
            int col = (c < 4) ? (lane * 4 + c) : (128 + lane * 4 + (c - 4));
            float zz = S.zsn[col];
            float lo, hi;
            unpack2(acc[p][c], lo, hi);
            s0 += lo * lo; d0 += lo * zz;
            s1 += hi * hi; d1 += hi * zz;
        }
        ssq[2 * p] = s0; dt[2 * p] = d0;
        ssq[2 * p + 1] = s1; dt[2 * p + 1] = d1;
    }
#pragma unroll
    for (int i = 0; i < 16; i++) {
#pragma unroll
        for (int off = 16; off > 0; off >>= 1) {
            ssq[i] += __shfl_xor_sync(0xFFFFFFFFu, ssq[i], off);
            dt[i]  += __shfl_xor_sync(0xFFFFFFFFu, dt[i],  off);
        }
    }
    if (lane == 0) {
        double wacc = 0.0;
#pragma unroll
        for (int i = 0; i < 16; i++) {
            float e = dt[i] / fmaxf(sqrtf(ssq[i]), 1e-12f);
            out[OFF_E + m0 + w * 16 + i] = e;
            wacc += (double)e;
        }
        S.wsum[w] = wacc;
    }
    __syncthreads();
    if (tid == 0) {
        double s = 0.0;
        for (int ww = 0; ww < 8; ww++) s += S.wsum[ww];
        g_part[blockIdx.x] = s;
    }
}

// ============================================================
// Kernel C: starts / ends from e
// ============================================================
__global__ void k_intervals(const float* __restrict__ out_ro, float* __restrict__ out) {
    int m = blockIdx.x * blockDim.x + threadIdx.x;
    if (m >= M_TOTAL) return;
    int v = m >> 13;          // /8192
    int t = m & (NT - 1);
    float r = g_rview[v];
    const float* e = out_ro + OFF_E;
    bool I  = e[m] >= r;
    bool Ip = (t > 0)      ? (e[m - 1] >= r) : false;
    bool In = (t < NT - 1) ? (e[m + 1] >= r) : false;
    out[OFF_ST + m] = (I && !Ip) ? 1.0f : 0.0f;
    out[OFF_EN + m] = (I && !In) ? 1.0f : 0.0f;
}

// ============================================================
// Kernel D: E_view, I_view, flag_unknown
// ============================================================
__global__ void k_final(float* __restrict__ out) {
    int t = threadIdx.x;  // 64 threads
    double s = 0.0;
    const int per_view = NT / BM;  // 64 CTAs per view
    for (int i = 0; i < per_view; i++) s += g_part[t * per_view + i];
    float ev = (float)(s / (double)NT);
    out[OFF_EV + t] = ev;
    bool iv = ev >= g_rview[t];
    out[OFF_IV + t] = iv ? 1.0f : 0.0f;
    int any = __syncthreads_or(iv ? 1 : 0);
    if (t == 0)
        out[OFF_FLAG] = ((out[OFF_PDET] >= 0.5f) && !any) ? 1.0f : 0.0f;
}

// ============================================================
extern "C" void kernel_launch(void* const* d_in, const int* in_sizes, int n_in,
                              void* d_out, int out_size) {
    const float* h      = (const float*)d_in[0];
    const float* alpha  = (const float*)d_in[1];
    const float* pi     = (const float*)d_in[2];
    const float* US     = (const float*)d_in[3];
    // d_in[4]=Wc_w, d_in[5]=Wc_b : unused downstream (zc dead)
    const float* Ws_w   = (const float*)d_in[6];
    const float* Ws_b   = (const float*)d_in[7];
    const float* det_w  = (const float*)d_in[8];
    const float* det_b  = (const float*)d_in[9];
    const float* cls_w  = (const float*)d_in[10];
    const float* cls_b  = (const float*)d_in[11];
    const float* Wwin   = (const float*)d_in[12];
    const float* tau_c0 = (const float*)d_in[13];
    const float* lamU   = (const float*)d_in[14];
    const float* lamC   = (const float*)d_in[15];
    const float* lamP   = (const float*)d_in[16];
    const float* lamPi  = (const float*)d_in[17];
    const float* nu     = (const float*)d_in[18];
    const float* risk   = (const float*)d_in[19];
    float* out = (float*)d_out;

    static bool attr_set = false;
    if (!attr_set) {
        cudaFuncSetAttribute(k_gemm, cudaFuncAttributeMaxDynamicSharedMemorySize,
                             (int)sizeof(SmemB));
        attr_set = true;
    }

    k_transpose<<<dim3(8, 8), dim3(32, 8)>>>(Wwin);
    k_scalars<<<1, 256>>>(alpha, pi, US, Ws_w, Ws_b, det_w, det_b, cls_w, cls_b,
                          tau_c0, lamU, lamC, lamP, lamPi, nu, risk, out);
    k_gemm<<<GEMM_BLOCKS, 256, sizeof(SmemB)>>>(h, out);
    k_intervals<<<(M_TOTAL + 255) / 256, 256>>>(out, out);
    k_final<<<1, NV>>>(out);
}